// round 3
// baseline (speedup 1.0000x reference)
#include <cuda_runtime.h>

#define H     51
#define G     204
#define GP    102          // gate pairs
#define BB    8            // batch per CTA
#define TPB   416          // 13 warps; 408 active in gate phase
#define NCTA  128
#define T_IN  512
#define T_FUT 64
#define T_TOT (T_IN + T_FUT)
#define CHUNK 32
#define HROW  12           // padded state row (48B) -> conflict-free banks

typedef unsigned long long ull;

struct __align__(16) Smem {
    float2 W1p[H][GP];       // W_hh1 as (even,odd) gate pairs, [k][gp]
    float2 W2p[2 * H][GP];   // rows 0..50 = W_ih2 (input h1), 51..101 = W_hh2
    float2 W3p[2 * H][GP];   // rows 0..50 = W_ih3 (input h2), 51..101 = W_hh3
    float  W1x[G];           // W_ih1 (input dim 1)
    float  b1[G], b2[G], b3[G];
    float  wlin[52];
    float  blin;
    float  pad0[3];
    float  hcat[3 * H][HROW];  // h1|h2|h3 concatenated, padded rows
    float  c[3][H][BB];
    float  gbuf[G][BB];
    float  xin[BB][CHUNK];
    float  xcur[BB];
};

__device__ __forceinline__ ull pack2(float x) {
    ull r; asm("mov.b64 %0, {%1, %1};" : "=l"(r) : "f"(x)); return r;
}
__device__ __forceinline__ ull fma2(ull a, ull b, ull c) {
    ull d; asm("fma.rn.f32x2 %0, %1, %2, %3;" : "=l"(d) : "l"(a), "l"(b), "l"(c)); return d;
}
__device__ __forceinline__ ull add2(ull a, ull b) {
    ull d; asm("add.rn.f32x2 %0, %1, %2;" : "=l"(d) : "l"(a), "l"(b)); return d;
}

__device__ __forceinline__ float sigf(float x) {
    return __fdividef(1.0f, 1.0f + __expf(-x));
}
__device__ __forceinline__ float tanh_(float x) {
    return 1.0f - __fdividef(2.0f, __expf(2.0f * x) + 1.0f);
}

// 16 MACs per k: weight pair (LDS.64) x state row broadcast (2x LDS.128)
__device__ __forceinline__ void kloop(ull acc[8],
                                      const float2 (*__restrict__ Wp)[GP],
                                      const float (*__restrict__ V)[HROW],
                                      int gp, int k0, int k1) {
#pragma unroll 2
    for (int k = k0; k < k1; k++) {
        float2 w  = Wp[k][gp];
        ull    wx = pack2(w.x), wy = pack2(w.y);
        ulonglong2 va = *(const ulonglong2 *)&V[k][0];
        ulonglong2 vb = *(const ulonglong2 *)&V[k][4];
        acc[0] = fma2(wx, va.x, acc[0]);
        acc[1] = fma2(wx, va.y, acc[1]);
        acc[2] = fma2(wx, vb.x, acc[2]);
        acc[3] = fma2(wx, vb.y, acc[3]);
        acc[4] = fma2(wy, va.x, acc[4]);
        acc[5] = fma2(wy, va.y, acc[5]);
        acc[6] = fma2(wy, vb.x, acc[6]);
        acc[7] = fma2(wy, vb.y, acc[7]);
    }
}

// combine the 4 kq partial sums via butterfly shuffle; kq==0 lane stores
__device__ __forceinline__ void reduce_store(ull acc[8], float *gb) {
#pragma unroll
    for (int i = 0; i < 8; i++)
        acc[i] = add2(acc[i], __shfl_xor_sync(0xffffffffu, acc[i], 1, 4));
#pragma unroll
    for (int i = 0; i < 8; i++)
        acc[i] = add2(acc[i], __shfl_xor_sync(0xffffffffu, acc[i], 2, 4));
    if (gb) {
        ulonglong2 v;
        v.x = acc[0]; v.y = acc[1]; *(ulonglong2 *)(gb + 0)  = v;
        v.x = acc[2]; v.y = acc[3]; *(ulonglong2 *)(gb + 4)  = v;
        v.x = acc[4]; v.y = acc[5]; *(ulonglong2 *)(gb + 8)  = v;
        v.x = acc[6]; v.y = acc[7]; *(ulonglong2 *)(gb + 12) = v;
    }
}

__device__ __forceinline__ void cell(Smem *s, int layer) {
    int tid = threadIdx.x;
    if (tid < H * BB) {
        int   j  = tid >> 3, b = tid & 7;
        float gi = s->gbuf[j][b];
        float gf = s->gbuf[H + j][b];
        float gg = s->gbuf[2 * H + j][b];
        float go = s->gbuf[3 * H + j][b];
        float cp = s->c[layer][j][b];
        float cn = sigf(gf) * cp + sigf(gi) * tanh_(gg);
        s->c[layer][j][b]       = cn;
        s->hcat[layer * H + j][b] = sigf(go) * tanh_(cn);
    }
}

__global__ void __launch_bounds__(TPB, 1)
lstm_seq_kernel(const float *__restrict__ input,
                const float *__restrict__ W_ih1, const float *__restrict__ W_hh1,
                const float *__restrict__ b_ih1, const float *__restrict__ b_hh1,
                const float *__restrict__ W_ih2, const float *__restrict__ W_hh2,
                const float *__restrict__ b_ih2, const float *__restrict__ b_hh2,
                const float *__restrict__ W_ih3, const float *__restrict__ W_hh3,
                const float *__restrict__ b_ih3, const float *__restrict__ b_hh3,
                const float *__restrict__ W_lin, const float *__restrict__ b_lin,
                float *__restrict__ out) {
    extern __shared__ char raw[];
    Smem *s = (Smem *)raw;

    const int  tid    = threadIdx.x;
    const int  b0     = blockIdx.x * BB;
    const int  gp     = min(tid >> 2, GP - 1);
    const int  kq     = tid & 3;
    const bool gvalid = (tid < 4 * GP) && (kq == 0);
    float *gdst0 = gvalid ? &s->gbuf[2 * gp][0] : (float *)0;

    // ---- one-time staging ----
    for (int idx = tid; idx < G; idx += TPB) {
        s->W1x[idx] = W_ih1[idx];
        s->b1[idx]  = b_ih1[idx] + b_hh1[idx];
        s->b2[idx]  = b_ih2[idx] + b_hh2[idx];
        s->b3[idx]  = b_ih3[idx] + b_hh3[idx];
    }
    for (int idx = tid; idx < H * GP; idx += TPB) {
        int k = idx / GP, g2 = idx % GP;
        s->W1p[k][g2] = make_float2(W_hh1[(2 * g2) * H + k],
                                    W_hh1[(2 * g2 + 1) * H + k]);
    }
    for (int idx = tid; idx < 2 * H * GP; idx += TPB) {
        int k = idx / GP, g2 = idx % GP;
        int kk = (k < H) ? k : k - H;
        const float *s2 = (k < H) ? W_ih2 : W_hh2;
        const float *s3 = (k < H) ? W_ih3 : W_hh3;
        s->W2p[k][g2] = make_float2(s2[(2 * g2) * H + kk], s2[(2 * g2 + 1) * H + kk]);
        s->W3p[k][g2] = make_float2(s3[(2 * g2) * H + kk], s3[(2 * g2 + 1) * H + kk]);
    }
    if (tid < H) s->wlin[tid] = W_lin[tid];
    if (tid == 0) s->blin = b_lin[0];
    for (int idx = tid; idx < 3 * H * HROW; idx += TPB) (&s->hcat[0][0])[idx] = 0.0f;
    for (int idx = tid; idx < 3 * H * BB; idx += TPB) (&s->c[0][0][0])[idx] = 0.0f;
    __syncthreads();

    for (int t = 0; t < T_TOT; t++) {
        if (t < T_IN && (t & (CHUNK - 1)) == 0) {
            for (int idx = tid; idx < BB * CHUNK; idx += TPB) {
                int r = idx / CHUNK, cx = idx % CHUNK;
                s->xin[r][cx] = input[(size_t)(b0 + r) * T_IN + t + cx];
            }
            __syncthreads();
        }
        if (t < T_IN && tid < BB) s->xcur[tid] = s->xin[tid][t & (CHUNK - 1)];
        __syncthreads();

        // ---- layer 1: x term + h1 (k split 13/13/13/12) ----
        {
            ull acc[8];
            if (kq == 0) {
                ull bx = pack2(s->b1[2 * gp]), by = pack2(s->b1[2 * gp + 1]);
                ull wx = pack2(s->W1x[2 * gp]), wy = pack2(s->W1x[2 * gp + 1]);
                ulonglong2 xa = *(const ulonglong2 *)&s->xcur[0];
                ulonglong2 xb = *(const ulonglong2 *)&s->xcur[4];
                acc[0] = fma2(wx, xa.x, bx); acc[1] = fma2(wx, xa.y, bx);
                acc[2] = fma2(wx, xb.x, bx); acc[3] = fma2(wx, xb.y, bx);
                acc[4] = fma2(wy, xa.x, by); acc[5] = fma2(wy, xa.y, by);
                acc[6] = fma2(wy, xb.x, by); acc[7] = fma2(wy, xb.y, by);
            } else {
#pragma unroll
                for (int i = 0; i < 8; i++) acc[i] = 0ull;
            }
            int k0 = kq * 13, k1 = min(H, k0 + 13);
            kloop(acc, s->W1p, s->hcat, gp, k0, k1);   // V rows 0..50 = h1
            reduce_store(acc, gdst0);
        }
        __syncthreads();
        cell(s, 0);
        __syncthreads();

        // ---- layer 2: concat(h1,h2) = hcat rows 0..101 (split 26/26/26/24) ----
        {
            ull acc[8];
            ull bx = (kq == 0) ? pack2(s->b2[2 * gp]) : 0ull;
            ull by = (kq == 0) ? pack2(s->b2[2 * gp + 1]) : 0ull;
#pragma unroll
            for (int i = 0; i < 4; i++) { acc[i] = bx; acc[4 + i] = by; }
            int k0 = kq * 26, k1 = min(2 * H, k0 + 26);
            kloop(acc, s->W2p, s->hcat, gp, k0, k1);
            reduce_store(acc, gdst0);
        }
        __syncthreads();
        cell(s, 1);
        __syncthreads();

        // ---- layer 3: concat(h2,h3) = hcat rows 51..152 ----
        {
            ull acc[8];
            ull bx = (kq == 0) ? pack2(s->b3[2 * gp]) : 0ull;
            ull by = (kq == 0) ? pack2(s->b3[2 * gp + 1]) : 0ull;
#pragma unroll
            for (int i = 0; i < 4; i++) { acc[i] = bx; acc[4 + i] = by; }
            int k0 = kq * 26, k1 = min(2 * H, k0 + 26);
            kloop(acc, s->W3p, &s->hcat[H], gp, k0, k1);
            reduce_store(acc, gdst0);
        }
        __syncthreads();
        cell(s, 2);
        __syncthreads();

        // ---- linear head + autoregressive feed ----
        if (tid < 64) {
            int   b = tid >> 3, r = tid & 7;
            float sum = 0.0f;
            for (int j = r; j < H; j += 8)
                sum = fmaf(s->wlin[j], s->hcat[2 * H + j][b], sum);
            sum += __shfl_down_sync(0xffffffffu, sum, 4, 8);
            sum += __shfl_down_sync(0xffffffffu, sum, 2, 8);
            sum += __shfl_down_sync(0xffffffffu, sum, 1, 8);
            if (r == 0) {
                float v = sum + s->blin;
                out[(size_t)(b0 + b) * T_TOT + t] = v;
                if (t >= T_IN - 1) s->xcur[b] = v;  // next-step input
            }
        }
        // loop-top __syncthreads orders xcur/out vs next step
    }
}

extern "C" void kernel_launch(void *const *d_in, const int *in_sizes, int n_in,
                              void *d_out, int out_size) {
    (void)in_sizes; (void)n_in; (void)out_size;
    cudaFuncSetAttribute(lstm_seq_kernel,
                         cudaFuncAttributeMaxDynamicSharedMemorySize,
                         (int)sizeof(Smem));
    lstm_seq_kernel<<<NCTA, TPB, sizeof(Smem)>>>(
        (const float *)d_in[0],
        (const float *)d_in[1], (const float *)d_in[2],
        (const float *)d_in[3], (const float *)d_in[4],
        (const float *)d_in[5], (const float *)d_in[6],
        (const float *)d_in[7], (const float *)d_in[8],
        (const float *)d_in[9], (const float *)d_in[10],
        (const float *)d_in[11], (const float *)d_in[12],
        (const float *)d_in[13], (const float *)d_in[14],
        (float *)d_out);
}

// round 4
// speedup vs baseline: 1.0009x; 1.0009x over previous
#include <cuda_runtime.h>

#define H     51
#define G     204
#define GP    102          // gate pairs
#define BB    8            // batch per CTA
#define TPB   416          // 13 warps; 408 active in gate phase
#define NCTA  128
#define T_IN  512
#define T_FUT 64
#define T_TOT (T_IN + T_FUT)
#define CHUNK 32
#define HROW  12           // padded state row (48B) -> conflict-free banks

typedef unsigned long long ull;

struct __align__(16) Smem {
    float2 W1p[H][GP];       // W_hh1 as (even,odd) gate pairs, [k][gp]
    float2 W2p[2 * H][GP];   // rows 0..50 = W_ih2 (input h1), 51..101 = W_hh2
    float2 W3p[2 * H][GP];   // rows 0..50 = W_ih3 (input h2), 51..101 = W_hh3
    float  W1x[G];           // W_ih1 (input dim 1)
    float  b1[G], b2[G], b3[G];
    float  wlin[52];
    float  blin;
    float  pad0[3];
    float  hcat[3 * H][HROW];  // h1|h2|h3 concatenated, padded rows
    float  c[3][H][BB];
    float  gbuf[G][BB];
    float  xin[BB][CHUNK];
    float  xcur[BB];
};

__device__ __forceinline__ ull pack2(float x) {
    ull r; asm("mov.b64 %0, {%1, %1};" : "=l"(r) : "f"(x)); return r;
}
__device__ __forceinline__ ull fma2(ull a, ull b, ull c) {
    ull d; asm("fma.rn.f32x2 %0, %1, %2, %3;" : "=l"(d) : "l"(a), "l"(b), "l"(c)); return d;
}
__device__ __forceinline__ ull add2(ull a, ull b) {
    ull d; asm("add.rn.f32x2 %0, %1, %2;" : "=l"(d) : "l"(a), "l"(b)); return d;
}

__device__ __forceinline__ float sigf(float x) {
    return __fdividef(1.0f, 1.0f + __expf(-x));
}
__device__ __forceinline__ float tanh_(float x) {
    return 1.0f - __fdividef(2.0f, __expf(2.0f * x) + 1.0f);
}

// 16 MACs per k: weight pair (LDS.64) x state row broadcast (2x LDS.128)
__device__ __forceinline__ void kloop(ull acc[8],
                                      const float2 (*__restrict__ Wp)[GP],
                                      const float (*__restrict__ V)[HROW],
                                      int gp, int k0, int k1) {
#pragma unroll 2
    for (int k = k0; k < k1; k++) {
        float2 w  = Wp[k][gp];
        ull    wx = pack2(w.x), wy = pack2(w.y);
        ulonglong2 va = *(const ulonglong2 *)&V[k][0];
        ulonglong2 vb = *(const ulonglong2 *)&V[k][4];
        acc[0] = fma2(wx, va.x, acc[0]);
        acc[1] = fma2(wx, va.y, acc[1]);
        acc[2] = fma2(wx, vb.x, acc[2]);
        acc[3] = fma2(wx, vb.y, acc[3]);
        acc[4] = fma2(wy, va.x, acc[4]);
        acc[5] = fma2(wy, va.y, acc[5]);
        acc[6] = fma2(wy, vb.x, acc[6]);
        acc[7] = fma2(wy, vb.y, acc[7]);
    }
}

// combine the 4 kq partial sums via butterfly shuffle; kq==0 lane stores
__device__ __forceinline__ void reduce_store(ull acc[8], float *gb) {
#pragma unroll
    for (int i = 0; i < 8; i++)
        acc[i] = add2(acc[i], __shfl_xor_sync(0xffffffffu, acc[i], 1, 4));
#pragma unroll
    for (int i = 0; i < 8; i++)
        acc[i] = add2(acc[i], __shfl_xor_sync(0xffffffffu, acc[i], 2, 4));
    if (gb) {
        ulonglong2 v;
        v.x = acc[0]; v.y = acc[1]; *(ulonglong2 *)(gb + 0)  = v;
        v.x = acc[2]; v.y = acc[3]; *(ulonglong2 *)(gb + 4)  = v;
        v.x = acc[4]; v.y = acc[5]; *(ulonglong2 *)(gb + 8)  = v;
        v.x = acc[6]; v.y = acc[7]; *(ulonglong2 *)(gb + 12) = v;
    }
}

__device__ __forceinline__ void cell(Smem *s, int layer) {
    int tid = threadIdx.x;
    if (tid < H * BB) {
        int   j  = tid >> 3, b = tid & 7;
        float gi = s->gbuf[j][b];
        float gf = s->gbuf[H + j][b];
        float gg = s->gbuf[2 * H + j][b];
        float go = s->gbuf[3 * H + j][b];
        float cp = s->c[layer][j][b];
        float cn = sigf(gf) * cp + sigf(gi) * tanh_(gg);
        s->c[layer][j][b]       = cn;
        s->hcat[layer * H + j][b] = sigf(go) * tanh_(cn);
    }
}

__global__ void __launch_bounds__(TPB, 1)
lstm_seq_kernel(const float *__restrict__ input,
                const float *__restrict__ W_ih1, const float *__restrict__ W_hh1,
                const float *__restrict__ b_ih1, const float *__restrict__ b_hh1,
                const float *__restrict__ W_ih2, const float *__restrict__ W_hh2,
                const float *__restrict__ b_ih2, const float *__restrict__ b_hh2,
                const float *__restrict__ W_ih3, const float *__restrict__ W_hh3,
                const float *__restrict__ b_ih3, const float *__restrict__ b_hh3,
                const float *__restrict__ W_lin, const float *__restrict__ b_lin,
                float *__restrict__ out) {
    extern __shared__ char raw[];
    Smem *s = (Smem *)raw;

    const int  tid    = threadIdx.x;
    const int  b0     = blockIdx.x * BB;
    const int  gp     = min(tid >> 2, GP - 1);
    const int  kq     = tid & 3;
    const bool gvalid = (tid < 4 * GP) && (kq == 0);
    float *gdst0 = gvalid ? &s->gbuf[2 * gp][0] : (float *)0;

    // ---- one-time staging ----
    for (int idx = tid; idx < G; idx += TPB) {
        s->W1x[idx] = W_ih1[idx];
        s->b1[idx]  = b_ih1[idx] + b_hh1[idx];
        s->b2[idx]  = b_ih2[idx] + b_hh2[idx];
        s->b3[idx]  = b_ih3[idx] + b_hh3[idx];
    }
    for (int idx = tid; idx < H * GP; idx += TPB) {
        int k = idx / GP, g2 = idx % GP;
        s->W1p[k][g2] = make_float2(W_hh1[(2 * g2) * H + k],
                                    W_hh1[(2 * g2 + 1) * H + k]);
    }
    for (int idx = tid; idx < 2 * H * GP; idx += TPB) {
        int k = idx / GP, g2 = idx % GP;
        int kk = (k < H) ? k : k - H;
        const float *s2 = (k < H) ? W_ih2 : W_hh2;
        const float *s3 = (k < H) ? W_ih3 : W_hh3;
        s->W2p[k][g2] = make_float2(s2[(2 * g2) * H + kk], s2[(2 * g2 + 1) * H + kk]);
        s->W3p[k][g2] = make_float2(s3[(2 * g2) * H + kk], s3[(2 * g2 + 1) * H + kk]);
    }
    if (tid < H) s->wlin[tid] = W_lin[tid];
    if (tid == 0) s->blin = b_lin[0];
    for (int idx = tid; idx < 3 * H * HROW; idx += TPB) (&s->hcat[0][0])[idx] = 0.0f;
    for (int idx = tid; idx < 3 * H * BB; idx += TPB) (&s->c[0][0][0])[idx] = 0.0f;
    __syncthreads();

    for (int t = 0; t < T_TOT; t++) {
        if (t < T_IN && (t & (CHUNK - 1)) == 0) {
            for (int idx = tid; idx < BB * CHUNK; idx += TPB) {
                int r = idx / CHUNK, cx = idx % CHUNK;
                s->xin[r][cx] = input[(size_t)(b0 + r) * T_IN + t + cx];
            }
            __syncthreads();
        }
        if (t < T_IN && tid < BB) s->xcur[tid] = s->xin[tid][t & (CHUNK - 1)];
        __syncthreads();

        // ---- layer 1: x term + h1 (k split 13/13/13/12) ----
        {
            ull acc[8];
            if (kq == 0) {
                ull bx = pack2(s->b1[2 * gp]), by = pack2(s->b1[2 * gp + 1]);
                ull wx = pack2(s->W1x[2 * gp]), wy = pack2(s->W1x[2 * gp + 1]);
                ulonglong2 xa = *(const ulonglong2 *)&s->xcur[0];
                ulonglong2 xb = *(const ulonglong2 *)&s->xcur[4];
                acc[0] = fma2(wx, xa.x, bx); acc[1] = fma2(wx, xa.y, bx);
                acc[2] = fma2(wx, xb.x, bx); acc[3] = fma2(wx, xb.y, bx);
                acc[4] = fma2(wy, xa.x, by); acc[5] = fma2(wy, xa.y, by);
                acc[6] = fma2(wy, xb.x, by); acc[7] = fma2(wy, xb.y, by);
            } else {
#pragma unroll
                for (int i = 0; i < 8; i++) acc[i] = 0ull;
            }
            int k0 = kq * 13, k1 = min(H, k0 + 13);
            kloop(acc, s->W1p, s->hcat, gp, k0, k1);   // V rows 0..50 = h1
            reduce_store(acc, gdst0);
        }
        __syncthreads();
        cell(s, 0);
        __syncthreads();

        // ---- layer 2: concat(h1,h2) = hcat rows 0..101 (split 26/26/26/24) ----
        {
            ull acc[8];
            ull bx = (kq == 0) ? pack2(s->b2[2 * gp]) : 0ull;
            ull by = (kq == 0) ? pack2(s->b2[2 * gp + 1]) : 0ull;
#pragma unroll
            for (int i = 0; i < 4; i++) { acc[i] = bx; acc[4 + i] = by; }
            int k0 = kq * 26, k1 = min(2 * H, k0 + 26);
            kloop(acc, s->W2p, s->hcat, gp, k0, k1);
            reduce_store(acc, gdst0);
        }
        __syncthreads();
        cell(s, 1);
        __syncthreads();

        // ---- layer 3: concat(h2,h3) = hcat rows 51..152 ----
        {
            ull acc[8];
            ull bx = (kq == 0) ? pack2(s->b3[2 * gp]) : 0ull;
            ull by = (kq == 0) ? pack2(s->b3[2 * gp + 1]) : 0ull;
#pragma unroll
            for (int i = 0; i < 4; i++) { acc[i] = bx; acc[4 + i] = by; }
            int k0 = kq * 26, k1 = min(2 * H, k0 + 26);
            kloop(acc, s->W3p, &s->hcat[H], gp, k0, k1);
            reduce_store(acc, gdst0);
        }
        __syncthreads();
        cell(s, 2);
        __syncthreads();

        // ---- linear head + autoregressive feed ----
        if (tid < 64) {
            int   b = tid >> 3, r = tid & 7;
            float sum = 0.0f;
            for (int j = r; j < H; j += 8)
                sum = fmaf(s->wlin[j], s->hcat[2 * H + j][b], sum);
            sum += __shfl_down_sync(0xffffffffu, sum, 4, 8);
            sum += __shfl_down_sync(0xffffffffu, sum, 2, 8);
            sum += __shfl_down_sync(0xffffffffu, sum, 1, 8);
            if (r == 0) {
                float v = sum + s->blin;
                out[(size_t)(b0 + b) * T_TOT + t] = v;
                if (t >= T_IN - 1) s->xcur[b] = v;  // next-step input
            }
        }
        // loop-top __syncthreads orders xcur/out vs next step
    }
}

extern "C" void kernel_launch(void *const *d_in, const int *in_sizes, int n_in,
                              void *d_out, int out_size) {
    (void)in_sizes; (void)n_in; (void)out_size;
    cudaFuncSetAttribute(lstm_seq_kernel,
                         cudaFuncAttributeMaxDynamicSharedMemorySize,
                         (int)sizeof(Smem));
    lstm_seq_kernel<<<NCTA, TPB, sizeof(Smem)>>>(
        (const float *)d_in[0],
        (const float *)d_in[1], (const float *)d_in[2],
        (const float *)d_in[3], (const float *)d_in[4],
        (const float *)d_in[5], (const float *)d_in[6],
        (const float *)d_in[7], (const float *)d_in[8],
        (const float *)d_in[9], (const float *)d_in[10],
        (const float *)d_in[11], (const float *)d_in[12],
        (const float *)d_in[13], (const float *)d_in[14],
        (float *)d_out);
}

// round 7
// speedup vs baseline: 1.5396x; 1.5381x over previous
#include <cuda_runtime.h>

#define H     51
#define G     204
#define BB    8
#define TPB   384
#define NCTA  128
#define T_IN  512
#define T_FUT 64
#define T_TOT 576
#define NTICK 514

typedef unsigned long long ull;

struct __align__(16) Smem {
    float2 W1[H + 1][102];   // k=0: W_ih1; k=1..51: W_hh1 col k-1; pair (ga,gb)
    float2 W2[2 * H][102];   // k=0..50: W_ih2 col k; 51..101: W_hh2 col k-51
    float2 W3[2 * H][102];
    float2 bp[3][102];       // bias pairs (b[ga], b[gb])
    float  wlin[52];
    float  blin;
    float  padA[3];
    float  hcat[154][BB];    // row 0 = x; 1..51 = h1; 52..102 = h2; 103..153 = h3
};

__device__ __forceinline__ ull pack2(float x) {
    ull r; asm("mov.b64 %0, {%1, %1};" : "=l"(r) : "f"(x)); return r;
}
__device__ __forceinline__ void unpack2(ull v, float &a, float &b) {
    asm("mov.b64 {%0, %1}, %2;" : "=f"(a), "=f"(b) : "l"(v));
}
__device__ __forceinline__ ull fma2(ull a, ull b, ull c) {
    ull d; asm("fma.rn.f32x2 %0, %1, %2, %3;" : "=l"(d) : "l"(a), "l"(b), "l"(c)); return d;
}
__device__ __forceinline__ float sigf(float x) {
    return __fdividef(1.0f, 1.0f + __expf(-x));
}
__device__ __forceinline__ float tanh_(float x) {
    return 1.0f - __fdividef(2.0f, __expf(2.0f * x) + 1.0f);
}

// gate_a x 8bb (acc[0..3]) and gate_b x 8bb (acc[4..7]) vs broadcast state row
__device__ __forceinline__ void mac8(ull acc[8], float2 w, const float *row) {
    ulonglong2 va = *(const ulonglong2 *)row;
    ulonglong2 vb = *(const ulonglong2 *)(row + 4);
    ull wx = pack2(w.x), wy = pack2(w.y);
    acc[0] = fma2(wx, va.x, acc[0]); acc[1] = fma2(wx, va.y, acc[1]);
    acc[2] = fma2(wx, vb.x, acc[2]); acc[3] = fma2(wx, vb.y, acc[3]);
    acc[4] = fma2(wy, va.x, acc[4]); acc[5] = fma2(wy, va.y, acc[5]);
    acc[6] = fma2(wy, vb.x, acc[6]); acc[7] = fma2(wy, vb.y, acc[7]);
}

// gates for layer `lay`, thread pair-slot lc (compile-time lay via unrolled callers)
__device__ __forceinline__ void layer_gates(const Smem *s, int lay, int lc, ull acc[8]) {
    float2 bv = s->bp[lay][lc];
    ull bx = pack2(bv.x), by = pack2(bv.y);
#pragma unroll
    for (int i = 0; i < 4; i++) { acc[i] = bx; acc[4 + i] = by; }
    if (lay == 0) {
#pragma unroll 4
        for (int k = 0; k < H + 1; k++) mac8(acc, s->W1[k][lc], &s->hcat[k][0]);
    } else if (lay == 1) {
#pragma unroll 3
        for (int k = 0; k < 2 * H; k++) mac8(acc, s->W2[k][lc], &s->hcat[1 + k][0]);
    } else {
#pragma unroll 3
        for (int k = 0; k < 2 * H; k++) mac8(acc, s->W3[k][lc], &s->hcat[52 + k][0]);
    }
}

// cell update for 4 batch elems; sel picks which packed halves are local
__device__ __forceinline__ void cell4(const ull acc[8], const ull prt[8], int sel,
                                      float creg[4], float hn[4]) {
    ull iv0, iv1, gv0, gv1, fv0, fv1, ov0, ov1;
    if (sel == 0) {
        iv0 = acc[0]; iv1 = acc[1]; gv0 = acc[4]; gv1 = acc[5];
        fv0 = prt[0]; fv1 = prt[1]; ov0 = prt[4]; ov1 = prt[5];
    } else {
        iv0 = prt[2]; iv1 = prt[3]; gv0 = prt[6]; gv1 = prt[7];
        fv0 = acc[2]; fv1 = acc[3]; ov0 = acc[6]; ov1 = acc[7];
    }
    float ig[4], fg[4], gg[4], og[4];
    unpack2(iv0, ig[0], ig[1]); unpack2(iv1, ig[2], ig[3]);
    unpack2(fv0, fg[0], fg[1]); unpack2(fv1, fg[2], fg[3]);
    unpack2(gv0, gg[0], gg[1]); unpack2(gv1, gg[2], gg[3]);
    unpack2(ov0, og[0], og[1]); unpack2(ov1, og[2], og[3]);
#pragma unroll
    for (int u = 0; u < 4; u++) {
        float cn = sigf(fg[u]) * creg[u] + sigf(ig[u]) * tanh_(gg[u]);
        hn[u]    = sigf(og[u]) * tanh_(cn);
        creg[u]  = cn;
    }
}

__device__ __forceinline__ float head_dot(const Smem *s, int b) {
    float sum = s->blin;
#pragma unroll 3
    for (int j = 0; j < H; j++) sum = fmaf(s->wlin[j], s->hcat[103 + j][b], sum);
    return sum;
}

__global__ void __launch_bounds__(TPB, 1)
lstm_seq_kernel(const float *__restrict__ input,
                const float *__restrict__ W_ih1, const float *__restrict__ W_hh1,
                const float *__restrict__ b_ih1, const float *__restrict__ b_hh1,
                const float *__restrict__ W_ih2, const float *__restrict__ W_hh2,
                const float *__restrict__ b_ih2, const float *__restrict__ b_hh2,
                const float *__restrict__ W_ih3, const float *__restrict__ W_hh3,
                const float *__restrict__ b_ih3, const float *__restrict__ b_hh3,
                const float *__restrict__ W_lin, const float *__restrict__ b_lin,
                float *__restrict__ out) {
    extern __shared__ char raw[];
    Smem *s = (Smem *)raw;

    const int tid = threadIdx.x;
    const int b0  = blockIdx.x * BB;
    const int L   = tid >> 7;       // layer block: warps 0-3 / 4-7 / 8-11
    const int l   = tid & 127;      // pair slot if < 102
    const int lc  = (l < 102) ? l : 101;
    const int j   = lc >> 1;
    const int sel = lc & 1;
    const bool gate_lane = (l < 102);
    const bool head_lane = (L == 0) && (l >= 102) && (l < 102 + BB);
    const bool xf_lane   = (L == 1) && (l >= 102) && (l < 102 + BB);

    // ---- one-time staging: pair layout (ga, gb) = (j+sel*51, j+sel*51+102) ----
    for (int idx = tid; idx < (H + 1) * 102; idx += TPB) {
        int k = idx / 102, l2 = idx % 102;
        int ga = (l2 >> 1) + (l2 & 1) * 51, gb = ga + 102;
        float2 v;
        if (k == 0) v = make_float2(W_ih1[ga], W_ih1[gb]);
        else        v = make_float2(W_hh1[ga * H + k - 1], W_hh1[gb * H + k - 1]);
        s->W1[k][l2] = v;
    }
    for (int idx = tid; idx < 2 * H * 102; idx += TPB) {
        int k = idx / 102, l2 = idx % 102;
        int ga = (l2 >> 1) + (l2 & 1) * 51, gb = ga + 102;
        int kk = (k < H) ? k : k - H;
        const float *s2 = (k < H) ? W_ih2 : W_hh2;
        const float *s3 = (k < H) ? W_ih3 : W_hh3;
        s->W2[k][l2] = make_float2(s2[ga * H + kk], s2[gb * H + kk]);
        s->W3[k][l2] = make_float2(s3[ga * H + kk], s3[gb * H + kk]);
    }
    for (int idx = tid; idx < 3 * 102; idx += TPB) {
        int ly = idx / 102, l2 = idx % 102;
        int ga = (l2 >> 1) + (l2 & 1) * 51, gb = ga + 102;
        const float *bi = (ly == 0) ? b_ih1 : (ly == 1) ? b_ih2 : b_ih3;
        const float *bh = (ly == 0) ? b_hh1 : (ly == 1) ? b_hh2 : b_hh3;
        s->bp[ly][l2] = make_float2(bi[ga] + bh[ga], bi[gb] + bh[gb]);
    }
    if (tid < H) s->wlin[tid] = W_lin[tid];
    if (tid == 0) s->blin = b_lin[0];
    for (int idx = tid; idx < 153 * BB; idx += TPB) (&s->hcat[1][0])[idx] = 0.0f;
    if (tid < BB) s->hcat[0][tid] = input[(size_t)(b0 + tid) * T_IN];  // x(0)
    __syncthreads();

    float creg[4] = {0.f, 0.f, 0.f, 0.f};   // c-state, batch sel*4..sel*4+3

    // ===== pipelined main loop: tick t -> L1@t, L2@t-1, L3@t-2 =====
    for (int t = 0; t < NTICK; t++) {
        ull   acc[8] = {};
        float xr = 0.0f;
        // ---- phase A: reads only ----
        if (gate_lane) {
            if (L == 0)      layer_gates(s, 0, lc, acc);
            else if (L == 1) layer_gates(s, 1, lc, acc);
            else             layer_gates(s, 2, lc, acc);
        } else if (head_lane && t >= 3) {
            int b = l - 102;
            out[(size_t)(b0 + b) * T_TOT + (t - 3)] = head_dot(s, b);
        } else if (xf_lane && t + 1 < T_IN) {
            xr = input[(size_t)(b0 + l - 102) * T_IN + t + 1];
        }
        ull prt[8];
#pragma unroll
        for (int i = 0; i < 8; i++) prt[i] = __shfl_xor_sync(0xffffffffu, acc[i], 1);

        const bool valid = gate_lane &&
            ((L == 0) ? (t <= T_IN - 1)
                      : (L == 1) ? (t >= 1 && t <= T_IN) : (t >= 2));
        float hn[4];
        if (valid) cell4(acc, prt, sel, creg, hn);
        __syncthreads();
        // ---- phase B: writes ----
        if (valid)
            *(float4 *)&s->hcat[1 + L * H + j][sel * 4] =
                make_float4(hn[0], hn[1], hn[2], hn[3]);
        if (xf_lane && t + 1 < T_IN) s->hcat[0][l - 102] = xr;
        __syncthreads();
    }

    // ---- drain: out(511) + first autoregressive input ----
    if (head_lane) {
        int b = l - 102;
        float v = head_dot(s, b);
        out[(size_t)(b0 + b) * T_TOT + (T_IN - 1)] = v;
        s->hcat[0][b] = v;
    }
    __syncthreads();

    // ===== autoregressive future: layer-serial, same machinery =====
    for (int fs = 0; fs < T_FUT; fs++) {
#pragma unroll
        for (int lay = 0; lay < 3; lay++) {
            ull acc[8] = {};
            const bool w = (L == lay) && gate_lane;
            if (w) layer_gates(s, lay, lc, acc);
            ull prt[8];
#pragma unroll
            for (int i = 0; i < 8; i++) prt[i] = __shfl_xor_sync(0xffffffffu, acc[i], 1);
            float hn[4];
            if (w) cell4(acc, prt, sel, creg, hn);
            __syncthreads();
            if (w)
                *(float4 *)&s->hcat[1 + lay * H + j][sel * 4] =
                    make_float4(hn[0], hn[1], hn[2], hn[3]);
            __syncthreads();
        }
        if (head_lane) {
            int b = l - 102;
            float v = head_dot(s, b);
            out[(size_t)(b0 + b) * T_TOT + T_IN + fs] = v;
            s->hcat[0][b] = v;
        }
        __syncthreads();
    }
}

extern "C" void kernel_launch(void *const *d_in, const int *in_sizes, int n_in,
                              void *d_out, int out_size) {
    (void)in_sizes; (void)n_in; (void)out_size;
    cudaFuncSetAttribute(lstm_seq_kernel,
                         cudaFuncAttributeMaxDynamicSharedMemorySize,
                         (int)sizeof(Smem));
    lstm_seq_kernel<<<NCTA, TPB, sizeof(Smem)>>>(
        (const float *)d_in[0],
        (const float *)d_in[1], (const float *)d_in[2],
        (const float *)d_in[3], (const float *)d_in[4],
        (const float *)d_in[5], (const float *)d_in[6],
        (const float *)d_in[7], (const float *)d_in[8],
        (const float *)d_in[9], (const float *)d_in[10],
        (const float *)d_in[11], (const float *)d_in[12],
        (const float *)d_in[13], (const float *)d_in[14],
        (float *)d_out);
}